// round 11
// baseline (speedup 1.0000x reference)
#include <cuda_runtime.h>

// Allpass biquad, fs=16000, f0=4000, Q=0.707. w0 = pi/2 exactly ->
// normalized: b0 = a2 = c, b2 = 1, b1 = a1 ~ 6e-17 (dropped).
// Closed FIR form: y[n] = c*x[n] + (1-c^2)*S[n],
//   S[n] = sum_{m=0..5} (-c)^m x[n-2-2m]    (tail (1-c^2)c^6 ~ 2.4e-5 << 1e-3)
//
// 16 outputs per thread: window = x[n0-12 .. n0+15] = 7 contiguous float4s.
// 7 LDG.128 + 4 STG.128 per 16 samples -> 0.086 L1 wavefronts/sample
// (0.109 at 8/thread, 0.156 at 4/thread). L1TEX is the measured limiter.

#define C_C  0.17149858514250882f
#define C_OM 0.97058823630252067f   /* 1 - c^2 */

#define THREADS 256
#define LVEC    4                    // output float4s per thread
#define NLD     7                    // window float4s per thread

__global__ __launch_bounds__(THREADS)
void allpass_fir16(const float4* __restrict__ x4,
                   float4* __restrict__ y4,
                   int NC)                           // 16-sample chunks per seq
{
    const int oc = blockIdx.x * THREADS + threadIdx.x;   // chunk index
    if (oc >= NC) return;

    const int f0  = LVEC * oc;                           // first output float4
    const int idx = blockIdx.y * (NC * LVEC) + f0;       // fits int32 (7.68M)

    const float4* p = x4 + idx;

    // ---- load window: float4s f0-3 .. f0+3  (w[j] = x[n0-12+j], j=0..27)
    float w[28];
    if (f0 >= 3) {
        #pragma unroll
        for (int j = 0; j < NLD; ++j) {
            const float4 v = __ldg(p + (j - 3));
            w[4 * j + 0] = v.x; w[4 * j + 1] = v.y;
            w[4 * j + 2] = v.z; w[4 * j + 3] = v.w;
        }
    } else {
        // sequence head (one thread per sequence): zero-pad = zero init state
        #pragma unroll
        for (int j = 0; j < NLD; ++j) {
            float4 v = make_float4(0.f, 0.f, 0.f, 0.f);
            if (f0 + (j - 3) >= 0) v = __ldg(p + (j - 3));
            w[4 * j + 0] = v.x; w[4 * j + 1] = v.y;
            w[4 * j + 2] = v.z; w[4 * j + 3] = v.w;
        }
    }

    // ---- S_i = sum_{m=0..5} (-c)^m w[10+i-2m]
    // i = 0,1 by Horner; i >= 2 by S_i = w[10+i] - c*S_{i-2}
    float S[16];
    {
        float s0 = w[0], s1 = w[1];
        #pragma unroll
        for (int j = 2; j <= 10; j += 2) {
            s0 = fmaf(-C_C, s0, w[j]);
            s1 = fmaf(-C_C, s1, w[j + 1]);
        }
        S[0] = s0; S[1] = s1;
    }
    #pragma unroll
    for (int i = 2; i < 16; ++i)
        S[i] = fmaf(-C_C, S[i - 2], w[10 + i]);

    // ---- y[n0+i] = c*x[n0+i] + (1-c^2)*S_i,  x[n0+i] = w[12+i]
    #pragma unroll
    for (int q = 0; q < LVEC; ++q) {
        float4 o;
        o.x = fmaf(C_OM, S[4 * q + 0], C_C * w[12 + 4 * q + 0]);
        o.y = fmaf(C_OM, S[4 * q + 1], C_C * w[12 + 4 * q + 1]);
        o.z = fmaf(C_OM, S[4 * q + 2], C_C * w[12 + 4 * q + 2]);
        o.w = fmaf(C_OM, S[4 * q + 3], C_C * w[12 + 4 * q + 3]);
        __stcs(y4 + idx + q, o);     // streaming store: keep L2 for x
    }
}

extern "C" void kernel_launch(void* const* d_in, const int* in_sizes, int n_in,
                              void* d_out, int out_size)
{
    const float4* x = (const float4*)d_in[0];
    float4*       y = (float4*)d_out;

    const int B  = 64;                   // fixed shape [64, 1, 480000]
    const int T  = in_sizes[0] / B;
    const int NC = T >> 4;               // 30000 chunks of 16 samples

    dim3 grid((NC + THREADS - 1) / THREADS, B, 1);
    allpass_fir16<<<grid, THREADS>>>(x, y, NC);
}

// round 12
// speedup vs baseline: 1.1617x; 1.1617x over previous
#include <cuda_runtime.h>

// Allpass biquad, fs=16000, f0=4000, Q=0.707. w0 = pi/2 exactly ->
// normalized: b0 = a2 = c, b2 = 1, b1 = a1 ~ 6e-17 (dropped).
// Closed FIR form: y[n] = c*x[n] + (1-c^2)*S[n],
//   S[n] = sum_{m=0..5} (-c)^m x[n-2-2m]    (tail (1-c^2)c^6 ~ 2.4e-5 << 1e-3)
//
// PAIR LAYOUT: lane handles output float4s f_a = warpBase+lane and f_b = f_a+32.
// All 8 loads + 2 stores per thread are perfectly coalesced warp instructions
// (lane stride 16B, 4 wavefronts each, 100% line utilization):
// 40 L1 wavefronts / 256 samples = 0.156 wf/sample (R8 was 0.219 at stride 32B).

#define C_C  0.17149858514250882f
#define C_OM 0.97058823630252067f   /* 1 - c^2 */

#define THREADS 256                  /* 8 warps */
#define F4_PER_WARP 64               /* output float4s per warp */

// One output float4 from its 16-float window w[0..15] = x[n0-12 .. n0+3]
__device__ __forceinline__ float4 fir_tap(const float4 v0, const float4 v1,
                                          const float4 v2, const float4 v3)
{
    float S0 = v0.x, S1 = v0.y;
    S0 = fmaf(-C_C, S0, v0.z);  S1 = fmaf(-C_C, S1, v0.w);
    S0 = fmaf(-C_C, S0, v1.x);  S1 = fmaf(-C_C, S1, v1.y);
    S0 = fmaf(-C_C, S0, v1.z);  S1 = fmaf(-C_C, S1, v1.w);
    S0 = fmaf(-C_C, S0, v2.x);  S1 = fmaf(-C_C, S1, v2.y);
    S0 = fmaf(-C_C, S0, v2.z);  S1 = fmaf(-C_C, S1, v2.w);
    const float S2 = fmaf(-C_C, S0, v3.x);   // S_i = x[n-2] - c*S_{i-2}
    const float S3 = fmaf(-C_C, S1, v3.y);

    float4 o;
    o.x = fmaf(C_OM, S0, C_C * v3.x);
    o.y = fmaf(C_OM, S1, C_C * v3.y);
    o.z = fmaf(C_OM, S2, C_C * v3.z);
    o.w = fmaf(C_OM, S3, C_C * v3.w);
    return o;
}

__global__ __launch_bounds__(THREADS)
void allpass_fir_pair(const float4* __restrict__ x4,
                      float4* __restrict__ y4,
                      int TV,                       // float4s per sequence
                      int WPS)                      // warps per sequence
{
    const int warp = blockIdx.x * (THREADS / 32) + (threadIdx.x >> 5);
    if (warp >= WPS) return;                        // warp-uniform tail guard

    const int  lane = threadIdx.x & 31;
    const int  wb   = warp * F4_PER_WARP;           // warp's first output float4
    const int  fa   = wb + lane;                    // this lane's 1st output
    const int  base = blockIdx.y * TV;              // int32 ok (7.68M total)

    const float4* pa = x4 + base + fa;
    const float4* pb = pa + 32;

    // ---- loads: 8 fully-coalesced LDG.128 (issue all early for MLP)
    float4 a0, a1, a2, a3, b0, b1, b2, b3;
    b0 = __ldg(pb - 3);  b1 = __ldg(pb - 2);
    b2 = __ldg(pb - 1);  b3 = __ldg(pb);
    if (wb != 0) {                                   // warp-uniform branch
        a0 = __ldg(pa - 3);  a1 = __ldg(pa - 2);
        a2 = __ldg(pa - 1);  a3 = __ldg(pa);
    } else {
        // first warp of each sequence: zero-pad = zero initial filter state
        const float4 z = make_float4(0.f, 0.f, 0.f, 0.f);
        a0 = (lane >= 3) ? __ldg(pa - 3) : z;
        a1 = (lane >= 2) ? __ldg(pa - 2) : z;
        a2 = (lane >= 1) ? __ldg(pa - 1) : z;
        a3 = __ldg(pa);
    }

    // ---- compute + coalesced streaming stores
    const float4 oa = fir_tap(a0, a1, a2, a3);
    __stcs(y4 + base + fa, oa);

    const float4 ob = fir_tap(b0, b1, b2, b3);
    __stcs(y4 + base + fa + 32, ob);
}

extern "C" void kernel_launch(void* const* d_in, const int* in_sizes, int n_in,
                              void* d_out, int out_size)
{
    const float4* x = (const float4*)d_in[0];
    float4*       y = (float4*)d_out;

    const int B   = 64;                   // fixed shape [64, 1, 480000]
    const int T   = in_sizes[0] / B;
    const int TV  = T >> 2;               // 120000 float4s per sequence
    const int WPS = TV / F4_PER_WARP;     // 1875 warps per sequence

    const int wpb = THREADS / 32;         // 8 warps per block
    dim3 grid((WPS + wpb - 1) / wpb, B, 1);
    allpass_fir_pair<<<grid, THREADS>>>(x, y, TV, WPS);
}

// round 13
// speedup vs baseline: 1.1644x; 1.0023x over previous
#include <cuda_runtime.h>

// Allpass biquad, fs=16000, f0=4000, Q=0.707. w0 = pi/2 exactly ->
// normalized: b0 = a2 = c, b2 = 1, b1 = a1 ~ 6e-17 (dropped).
// Closed FIR form: y[n] = c*x[n] + (1-c^2)*S[n],
//   S[n] = sum_{m=0..5} (-c)^m x[n-2-2m]    (tail (1-c^2)c^6 ~ 2.4e-5 << 1e-3)
//
// PAIR LAYOUT: lane handles output float4s f_a = warpBase+lane and f_b = f_a+32.
// All 8 loads + 2 stores per thread are perfectly coalesced warp instructions
// (lane stride 16B, 4 wavefronts each, 100% line utilization):
// 40 L1 wavefronts / 256 samples = 0.156 wf/sample (R8 was 0.219 at stride 32B).

#define C_C  0.17149858514250882f
#define C_OM 0.97058823630252067f   /* 1 - c^2 */

#define THREADS 256                  /* 8 warps */
#define F4_PER_WARP 64               /* output float4s per warp */

// One output float4 from its 16-float window w[0..15] = x[n0-12 .. n0+3]
__device__ __forceinline__ float4 fir_tap(const float4 v0, const float4 v1,
                                          const float4 v2, const float4 v3)
{
    float S0 = v0.x, S1 = v0.y;
    S0 = fmaf(-C_C, S0, v0.z);  S1 = fmaf(-C_C, S1, v0.w);
    S0 = fmaf(-C_C, S0, v1.x);  S1 = fmaf(-C_C, S1, v1.y);
    S0 = fmaf(-C_C, S0, v1.z);  S1 = fmaf(-C_C, S1, v1.w);
    S0 = fmaf(-C_C, S0, v2.x);  S1 = fmaf(-C_C, S1, v2.y);
    S0 = fmaf(-C_C, S0, v2.z);  S1 = fmaf(-C_C, S1, v2.w);
    const float S2 = fmaf(-C_C, S0, v3.x);   // S_i = x[n-2] - c*S_{i-2}
    const float S3 = fmaf(-C_C, S1, v3.y);

    float4 o;
    o.x = fmaf(C_OM, S0, C_C * v3.x);
    o.y = fmaf(C_OM, S1, C_C * v3.y);
    o.z = fmaf(C_OM, S2, C_C * v3.z);
    o.w = fmaf(C_OM, S3, C_C * v3.w);
    return o;
}

__global__ __launch_bounds__(THREADS)
void allpass_fir_pair(const float4* __restrict__ x4,
                      float4* __restrict__ y4,
                      int TV,                       // float4s per sequence
                      int WPS)                      // warps per sequence
{
    const int warp = blockIdx.x * (THREADS / 32) + (threadIdx.x >> 5);
    if (warp >= WPS) return;                        // warp-uniform tail guard

    const int  lane = threadIdx.x & 31;
    const int  wb   = warp * F4_PER_WARP;           // warp's first output float4
    const int  fa   = wb + lane;                    // this lane's 1st output
    const int  base = blockIdx.y * TV;              // int32 ok (7.68M total)

    const float4* pa = x4 + base + fa;
    const float4* pb = pa + 32;

    // ---- loads: 8 fully-coalesced LDG.128 (issue all early for MLP)
    float4 a0, a1, a2, a3, b0, b1, b2, b3;
    b0 = __ldg(pb - 3);  b1 = __ldg(pb - 2);
    b2 = __ldg(pb - 1);  b3 = __ldg(pb);
    if (wb != 0) {                                   // warp-uniform branch
        a0 = __ldg(pa - 3);  a1 = __ldg(pa - 2);
        a2 = __ldg(pa - 1);  a3 = __ldg(pa);
    } else {
        // first warp of each sequence: zero-pad = zero initial filter state
        const float4 z = make_float4(0.f, 0.f, 0.f, 0.f);
        a0 = (lane >= 3) ? __ldg(pa - 3) : z;
        a1 = (lane >= 2) ? __ldg(pa - 2) : z;
        a2 = (lane >= 1) ? __ldg(pa - 1) : z;
        a3 = __ldg(pa);
    }

    // ---- compute + coalesced streaming stores
    const float4 oa = fir_tap(a0, a1, a2, a3);
    __stcs(y4 + base + fa, oa);

    const float4 ob = fir_tap(b0, b1, b2, b3);
    __stcs(y4 + base + fa + 32, ob);
}

extern "C" void kernel_launch(void* const* d_in, const int* in_sizes, int n_in,
                              void* d_out, int out_size)
{
    const float4* x = (const float4*)d_in[0];
    float4*       y = (float4*)d_out;

    const int B   = 64;                   // fixed shape [64, 1, 480000]
    const int T   = in_sizes[0] / B;
    const int TV  = T >> 2;               // 120000 float4s per sequence
    const int WPS = TV / F4_PER_WARP;     // 1875 warps per sequence

    const int wpb = THREADS / 32;         // 8 warps per block
    dim3 grid((WPS + wpb - 1) / wpb, B, 1);
    allpass_fir_pair<<<grid, THREADS>>>(x, y, TV, WPS);
}